// round 1
// baseline (speedup 1.0000x reference)
#include <cuda_runtime.h>
#include <cuda_bf16.h>
#include <cstdint>

// Problem constants (1, 768, 128, 128)
#define C_DIM 768
#define N_DIM 16384

// GEMM tiling
#define BM 128
#define BN 128
#define BK 32
#define NT (C_DIM / BK)   // 24 k-tiles
#define PAD 40            // smem row length in bf16 elems (80B row -> conflict-free frag loads)

// ---------------- scratch (no allocations allowed) ----------------
__device__ float g_inv_r[N_DIM];
__device__ float g_inv_s[N_DIM];
__device__ __nv_bfloat16 g_A[(size_t)N_DIM * C_DIM];   // normalized F_r, [n][c]
__device__ __nv_bfloat16 g_B[(size_t)N_DIM * C_DIM];   // normalized F_s, [m][c]
__device__ unsigned int g_rowmax[N_DIM];               // monotonic float keys

// monotonic float -> uint key (order-preserving for all finite floats)
__device__ __forceinline__ unsigned int fkey(float f) {
    unsigned int u = __float_as_uint(f);
    return (u & 0x80000000u) ? ~u : (u | 0x80000000u);
}

__device__ __forceinline__ uint32_t smem_u32(const void* p) {
    return (uint32_t)__cvta_generic_to_shared(p);
}

// ---------------- init row maxes ----------------
__global__ void init_rowmax_kernel() {
    int i = blockIdx.x * blockDim.x + threadIdx.x;
    if (i < N_DIM) g_rowmax[i] = 0u;  // below key of any finite float
}

// ---------------- inverse column norms: X is [C][N], norm over C ----------------
__global__ void colnorm_kernel(const float* __restrict__ X, int which) {
    __shared__ float red[256];
    int tid = threadIdx.x;
    int n = blockIdx.x * 64 + (tid & 63);
    int part = tid >> 6;                 // 4 partial sums along C
    const int CP = C_DIM / 4;            // 192
    const float* p = X + (size_t)part * CP * N_DIM + n;
    float s = 0.f;
    #pragma unroll 4
    for (int c = 0; c < CP; ++c) {
        float v = p[(size_t)c * N_DIM];
        s += v * v;
    }
    red[tid] = s;
    __syncthreads();
    if (tid < 64) {
        float t = red[tid] + red[tid + 64] + red[tid + 128] + red[tid + 192];
        float inv = 1.0f / fmaxf(sqrtf(t), 1e-12f);
        if (which) g_inv_s[n] = inv; else g_inv_r[n] = inv;
    }
}

// ---------------- transpose + normalize + bf16 convert: [C][N] -> [N][C] ----------------
__global__ void transpose_scale_kernel(const float* __restrict__ X, int which) {
    __shared__ float tile[32][33];
    const float* inv = which ? g_inv_s : g_inv_r;
    __nv_bfloat16* T = which ? g_B : g_A;
    int n0 = blockIdx.x * 32;
    int c0 = blockIdx.y * 32;
    int tx = threadIdx.x, ty = threadIdx.y;
    #pragma unroll
    for (int j = ty; j < 32; j += 8)
        tile[j][tx] = X[(size_t)(c0 + j) * N_DIM + n0 + tx];
    __syncthreads();
    #pragma unroll
    for (int j = ty; j < 32; j += 8) {
        int n = n0 + j;
        T[(size_t)n * C_DIM + c0 + tx] = __float2bfloat16(tile[tx][j] * inv[n]);
    }
}

// ---------------- fused GEMM + row-max ----------------
// C[n][m] = sum_c A[n][c] * B[m][c]; keep only per-row max.
__device__ __forceinline__ void load_tiles(
    __nv_bfloat16 (*sAbuf)[PAD], __nv_bfloat16 (*sBbuf)[PAD],
    const __nv_bfloat16* gAt, const __nv_bfloat16* gBt, int k0, int tid)
{
    #pragma unroll
    for (int p = 0; p < 2; ++p) {
        int chunk = tid + p * 256;       // 512 chunks of 16B cover 128x32 bf16
        int row = chunk >> 2;
        int cc  = (chunk & 3) * 8;
        uint32_t dA = smem_u32(&sAbuf[row][cc]);
        const __nv_bfloat16* sA_src = gAt + (size_t)row * C_DIM + k0 + cc;
        asm volatile("cp.async.cg.shared.global [%0], [%1], 16;" :: "r"(dA), "l"(sA_src));
        uint32_t dB = smem_u32(&sBbuf[row][cc]);
        const __nv_bfloat16* sB_src = gBt + (size_t)row * C_DIM + k0 + cc;
        asm volatile("cp.async.cg.shared.global [%0], [%1], 16;" :: "r"(dB), "l"(sB_src));
    }
    asm volatile("cp.async.commit_group;");
}

__global__ void __launch_bounds__(256) nnfm_gemm_kernel() {
    __shared__ __nv_bfloat16 sA[2][BM][PAD];
    __shared__ __nv_bfloat16 sB[2][BN][PAD];
    __shared__ unsigned int smax[BM];

    int tid  = threadIdx.x;
    int wid  = tid >> 5;
    int lane = tid & 31;
    int tileM = blockIdx.y, tileN = blockIdx.x;

    const __nv_bfloat16* gAt = g_A + (size_t)tileM * BM * C_DIM;
    const __nv_bfloat16* gBt = g_B + (size_t)tileN * BN * C_DIM;

    // warp grid 4 (M) x 2 (N); warp tile 32x64 = 2x8 frags of m16n8
    int mb = (wid >> 1) * 32;
    int nb = (wid & 1) * 64;

    float acc[2][8][4];
    #pragma unroll
    for (int mi = 0; mi < 2; ++mi)
        #pragma unroll
        for (int ni = 0; ni < 8; ++ni)
            #pragma unroll
            for (int q = 0; q < 4; ++q) acc[mi][ni][q] = 0.f;

    load_tiles(sA[0], sB[0], gAt, gBt, 0, tid);

    for (int kt = 0; kt < NT; ++kt) {
        int buf = kt & 1;
        if (kt + 1 < NT) {
            load_tiles(sA[buf ^ 1], sB[buf ^ 1], gAt, gBt, (kt + 1) * BK, tid);
            asm volatile("cp.async.wait_group 1;");
        } else {
            asm volatile("cp.async.wait_group 0;");
        }
        __syncthreads();

        #pragma unroll
        for (int ki = 0; ki < 2; ++ki) {
            int kk = ki * 16 + (lane & 3) * 2;
            uint32_t a[2][4], b[8][2];
            #pragma unroll
            for (int mi = 0; mi < 2; ++mi) {
                int r = mb + mi * 16 + (lane >> 2);
                a[mi][0] = *(const uint32_t*)&sA[buf][r][kk];
                a[mi][1] = *(const uint32_t*)&sA[buf][r + 8][kk];
                a[mi][2] = *(const uint32_t*)&sA[buf][r][kk + 8];
                a[mi][3] = *(const uint32_t*)&sA[buf][r + 8][kk + 8];
            }
            #pragma unroll
            for (int ni = 0; ni < 8; ++ni) {
                int rn = nb + ni * 8 + (lane >> 2);
                b[ni][0] = *(const uint32_t*)&sB[buf][rn][kk];
                b[ni][1] = *(const uint32_t*)&sB[buf][rn][kk + 8];
            }
            #pragma unroll
            for (int mi = 0; mi < 2; ++mi)
                #pragma unroll
                for (int ni = 0; ni < 8; ++ni) {
                    float* c = acc[mi][ni];
                    asm volatile(
                        "mma.sync.aligned.m16n8k16.row.col.f32.bf16.bf16.f32 "
                        "{%0,%1,%2,%3}, {%4,%5,%6,%7}, {%8,%9}, {%0,%1,%2,%3};"
                        : "+f"(c[0]), "+f"(c[1]), "+f"(c[2]), "+f"(c[3])
                        : "r"(a[mi][0]), "r"(a[mi][1]), "r"(a[mi][2]), "r"(a[mi][3]),
                          "r"(b[ni][0]), "r"(b[ni][1]));
                }
        }
        __syncthreads();
    }

    // ---- epilogue: per-row max of this 128x128 tile ----
    for (int i = tid; i < BM; i += 256) smax[i] = 0u;
    __syncthreads();

    #pragma unroll
    for (int mi = 0; mi < 2; ++mi) {
        float m0 = -3.402823466e38f, m1 = -3.402823466e38f;
        #pragma unroll
        for (int ni = 0; ni < 8; ++ni) {
            m0 = fmaxf(m0, fmaxf(acc[mi][ni][0], acc[mi][ni][1]));  // row = base + lane/4
            m1 = fmaxf(m1, fmaxf(acc[mi][ni][2], acc[mi][ni][3]));  // row = base + lane/4 + 8
        }
        m0 = fmaxf(m0, __shfl_xor_sync(0xffffffffu, m0, 1));
        m0 = fmaxf(m0, __shfl_xor_sync(0xffffffffu, m0, 2));
        m1 = fmaxf(m1, __shfl_xor_sync(0xffffffffu, m1, 1));
        m1 = fmaxf(m1, __shfl_xor_sync(0xffffffffu, m1, 2));
        if ((lane & 3) == 0) {
            int r = mb + mi * 16 + (lane >> 2);
            atomicMax(&smax[r], fkey(m0));
            atomicMax(&smax[r + 8], fkey(m1));
        }
    }
    __syncthreads();
    if (tid < BM) atomicMax(&g_rowmax[tileM * BM + tid], smax[tid]);
}

// ---------------- final: loss = mean(1 - rowmax) ----------------
__global__ void final_reduce_kernel(float* __restrict__ out) {
    __shared__ float red[256];
    int tid = threadIdx.x;
    float s = 0.f;
    for (int i = tid; i < N_DIM; i += 256) {
        unsigned int key = g_rowmax[i];
        float f = (key & 0x80000000u) ? __uint_as_float(key & 0x7FFFFFFFu)
                                      : __uint_as_float(~key);
        s += 1.0f - f;
    }
    red[tid] = s;
    __syncthreads();
    for (int off = 128; off > 0; off >>= 1) {
        if (tid < off) red[tid] += red[tid + off];
        __syncthreads();
    }
    if (tid == 0) out[0] = red[0] / (float)N_DIM;
}

// ---------------- launch ----------------
extern "C" void kernel_launch(void* const* d_in, const int* in_sizes, int n_in,
                              void* d_out, int out_size) {
    const float* F_r = (const float*)d_in[0];
    const float* F_s = (const float*)d_in[1];

    init_rowmax_kernel<<<N_DIM / 256, 256>>>();
    colnorm_kernel<<<N_DIM / 64, 256>>>(F_r, 0);
    colnorm_kernel<<<N_DIM / 64, 256>>>(F_s, 1);

    dim3 tb(32, 8);
    dim3 tg(N_DIM / 32, C_DIM / 32);
    transpose_scale_kernel<<<tg, tb>>>(F_r, 0);
    transpose_scale_kernel<<<tg, tb>>>(F_s, 1);

    dim3 gg(N_DIM / BN, N_DIM / BM);
    nnfm_gemm_kernel<<<gg, 256>>>();

    final_reduce_kernel<<<1, 256>>>((float*)d_out);
}

// round 3
// speedup vs baseline: 1.3526x; 1.3526x over previous
#include <cuda_runtime.h>
#include <cuda_bf16.h>
#include <cstdint>

// Problem constants (1, 768, 128, 128)
#define C_DIM 768
#define N_DIM 16384

// ---------------- GEMM tiling (mma.sync path; tcgen05 PTX rejected by toolchain) ----
#define BM 128            // CTA tile M (A rows -> rowmax rows)
#define BN 256            // CTA tile N (B rows)
#define KC 64             // K per chunk = 128 bytes/row
#define NCHUNK (C_DIM / KC)   // 12
#define NSTAGE 4

#define A_STAGE_BYTES (BM * 128)              // 16384
#define B_STAGE_BYTES (BN * 128)              // 32768
#define STAGE_BYTES (A_STAGE_BYTES + B_STAGE_BYTES)   // 49152
#define SMAX_OFF (NSTAGE * STAGE_BYTES)       // 196608
#define SMEM_TOTAL (SMAX_OFF + 512)

// ---------------- scratch (no allocations allowed) ----------------
__device__ float g_inv_r[N_DIM];
__device__ float g_inv_s[N_DIM];
__device__ __nv_bfloat16 g_A[(size_t)N_DIM * C_DIM];   // normalized F_r, [n][c]
__device__ __nv_bfloat16 g_B[(size_t)N_DIM * C_DIM];   // normalized F_s, [m][c]
__device__ unsigned int g_rowmax[N_DIM];               // monotonic float keys

__device__ __forceinline__ unsigned int fkey(float f) {
    unsigned int u = __float_as_uint(f);
    return (u & 0x80000000u) ? ~u : (u | 0x80000000u);
}
__device__ __forceinline__ uint32_t smem_u32(const void* p) {
    return (uint32_t)__cvta_generic_to_shared(p);
}

#define LDSM4(r0, r1, r2, r3, addr) \
    asm volatile("ldmatrix.sync.aligned.m8n8.x4.shared.b16 {%0,%1,%2,%3}, [%4];" \
                 : "=r"(r0), "=r"(r1), "=r"(r2), "=r"(r3) : "r"(addr))

// ---------------- init row maxes ----------------
__global__ void init_rowmax_kernel() {
    int i = blockIdx.x * blockDim.x + threadIdx.x;
    if (i < N_DIM) g_rowmax[i] = 0u;
}

// ---------------- inverse column norms: X is [C][N], norm over C ----------------
__global__ void colnorm_kernel(const float* __restrict__ X, int which) {
    __shared__ float red[256];
    int tid = threadIdx.x;
    int n = blockIdx.x * 64 + (tid & 63);
    int part = tid >> 6;
    const int CP = C_DIM / 4;
    const float* p = X + (size_t)part * CP * N_DIM + n;
    float s = 0.f;
    #pragma unroll 4
    for (int c = 0; c < CP; ++c) {
        float v = p[(size_t)c * N_DIM];
        s += v * v;
    }
    red[tid] = s;
    __syncthreads();
    if (tid < 64) {
        float t = red[tid] + red[tid + 64] + red[tid + 128] + red[tid + 192];
        float inv = 1.0f / fmaxf(sqrtf(t), 1e-12f);
        if (which) g_inv_s[n] = inv; else g_inv_r[n] = inv;
    }
}

// ---------------- transpose + normalize + bf16 convert: [C][N] -> [N][C] ----------------
__global__ void transpose_scale_kernel(const float* __restrict__ X, int which) {
    __shared__ float tile[32][33];
    const float* inv = which ? g_inv_s : g_inv_r;
    __nv_bfloat16* T = which ? g_B : g_A;
    int n0 = blockIdx.x * 32;
    int c0 = blockIdx.y * 32;
    int tx = threadIdx.x, ty = threadIdx.y;
    #pragma unroll
    for (int j = ty; j < 32; j += 8)
        tile[j][tx] = X[(size_t)(c0 + j) * N_DIM + n0 + tx];
    __syncthreads();
    #pragma unroll
    for (int j = ty; j < 32; j += 8) {
        int n = n0 + j;
        T[(size_t)n * C_DIM + c0 + tx] = __float2bfloat16(tile[tx][j] * inv[n]);
    }
}

// ---------------- fused GEMM + row-max ----------------
// smem tile layout: row = 128 bytes (64 bf16), 16B chunk ch swizzled:
//   off(row, ch) = row*128 + ((ch ^ (row&7)) << 4)
__device__ __forceinline__ void load_stage(uint32_t smem_base, int stage, int chunk,
                                           const __nv_bfloat16* gA,
                                           const __nv_bfloat16* gB, int tid) {
    uint32_t sA = smem_base + stage * STAGE_BYTES;
    uint32_t sB = sA + A_STAGE_BYTES;
    const __nv_bfloat16* srcA = gA + chunk * KC;
    const __nv_bfloat16* srcB = gB + chunk * KC;
    #pragma unroll
    for (int i = 0; i < 4; ++i) {            // A: 128 rows x 8 chunks = 1024
        int c = i * 256 + tid;
        int row = c >> 3, ch = c & 7;
        uint32_t off = row * 128 + ((ch ^ (row & 7)) << 4);
        const __nv_bfloat16* p = srcA + (size_t)row * C_DIM + ch * 8;
        asm volatile("cp.async.cg.shared.global [%0], [%1], 16;" :: "r"(sA + off), "l"(p));
    }
    #pragma unroll
    for (int i = 0; i < 8; ++i) {            // B: 256 rows x 8 chunks = 2048
        int c = i * 256 + tid;
        int row = c >> 3, ch = c & 7;
        uint32_t off = row * 128 + ((ch ^ (row & 7)) << 4);
        const __nv_bfloat16* p = srcB + (size_t)row * C_DIM + ch * 8;
        asm volatile("cp.async.cg.shared.global [%0], [%1], 16;" :: "r"(sB + off), "l"(p));
    }
    asm volatile("cp.async.commit_group;");
}

__global__ void __launch_bounds__(256, 1) nnfm_gemm_hmma() {
    extern __shared__ __align__(1024) char smem[];
    uint32_t smem_base = smem_u32(smem);
    unsigned int* smax = (unsigned int*)(smem + SMAX_OFF);

    int tid = threadIdx.x;
    int wid = tid >> 5;
    int lane = tid & 31;
    int tileM = blockIdx.y, tileN = blockIdx.x;

    const __nv_bfloat16* gA = g_A + (size_t)tileM * BM * C_DIM;
    const __nv_bfloat16* gB = g_B + (size_t)tileN * BN * C_DIM;

    // warp grid: 2 (M) x 4 (N); warp tile 64x64 = 4x8 frags of m16n8
    int mb = (wid >> 2) * 64;
    int nb = (wid & 3) * 64;

    // ---- precomputed ldmatrix lane addresses (XOR-swizzle folded) ----
    // A x4: lanes 0-7 rows+0 kEven | 8-15 rows+8 kEven | 16-23 rows+0 kOdd | 24-31 rows+8 kOdd
    int grpRowA = (lane & 7) + ((lane >> 3) & 1) * 8;
    uint32_t aKbit = (uint32_t)(lane >> 4) << 4;
    uint32_t baseA[4];
    #pragma unroll
    for (int mi = 0; mi < 4; ++mi) {
        int r = mb + mi * 16 + grpRowA;
        baseA[mi] = (smem_base + r * 128 + ((r & 7) << 4)) ^ aKbit;
    }
    // B x4: lanes 0-7 rows+0 kEven | 8-15 rows+0 kOdd | 16-23 rows+8 kEven | 24-31 rows+8 kOdd
    int grpRowB = (lane & 7) + ((lane >> 4) << 3);
    uint32_t bKbit = (uint32_t)((lane >> 3) & 1) << 4;
    uint32_t baseB[4];
    #pragma unroll
    for (int p = 0; p < 4; ++p) {
        int r = nb + p * 16 + grpRowB;
        baseB[p] = (smem_base + A_STAGE_BYTES + r * 128 + ((r & 7) << 4)) ^ bKbit;
    }

    float acc[4][8][4];
    #pragma unroll
    for (int mi = 0; mi < 4; ++mi)
        #pragma unroll
        for (int ni = 0; ni < 8; ++ni)
            #pragma unroll
            for (int q = 0; q < 4; ++q) acc[mi][ni][q] = 0.f;

    #pragma unroll
    for (int s = 0; s < NSTAGE - 1; ++s) load_stage(smem_base, s, s, gA, gB, tid);

    for (int k = 0; k < NCHUNK; ++k) {
        int st = k & (NSTAGE - 1);
        uint32_t stOff = st * STAGE_BYTES;
        asm volatile("cp.async.wait_group %0;" :: "n"(NSTAGE - 2));
        __syncthreads();

        if (k + NSTAGE - 1 < NCHUNK)
            load_stage(smem_base, (k + NSTAGE - 1) & (NSTAGE - 1), k + NSTAGE - 1, gA, gB, tid);
        else
            asm volatile("cp.async.commit_group;");   // keep group count stable

        #pragma unroll
        for (int ki = 0; ki < 4; ++ki) {
            uint32_t kx = (uint32_t)ki << 5;
            uint32_t a[4][4], b[8][2];
            #pragma unroll
            for (int mi = 0; mi < 4; ++mi)
                LDSM4(a[mi][0], a[mi][1], a[mi][2], a[mi][3], (baseA[mi] + stOff) ^ kx);
            #pragma unroll
            for (int p = 0; p < 4; ++p)
                LDSM4(b[2*p][0], b[2*p][1], b[2*p+1][0], b[2*p+1][1], (baseB[p] + stOff) ^ kx);
            #pragma unroll
            for (int mi = 0; mi < 4; ++mi)
                #pragma unroll
                for (int ni = 0; ni < 8; ++ni) {
                    float* c = acc[mi][ni];
                    asm volatile(
                        "mma.sync.aligned.m16n8k16.row.col.f32.bf16.bf16.f32 "
                        "{%0,%1,%2,%3}, {%4,%5,%6,%7}, {%8,%9}, {%0,%1,%2,%3};"
                        : "+f"(c[0]), "+f"(c[1]), "+f"(c[2]), "+f"(c[3])
                        : "r"(a[mi][0]), "r"(a[mi][1]), "r"(a[mi][2]), "r"(a[mi][3]),
                          "r"(b[ni][0]), "r"(b[ni][1]));
                }
        }
    }

    // ---- epilogue: per-row max of this 128x256 tile ----
    __syncthreads();
    if (tid < BM) smax[tid] = 0u;
    __syncthreads();

    #pragma unroll
    for (int mi = 0; mi < 4; ++mi) {
        float m0 = -3.402823466e38f, m1 = -3.402823466e38f;
        #pragma unroll
        for (int ni = 0; ni < 8; ++ni) {
            m0 = fmaxf(m0, fmaxf(acc[mi][ni][0], acc[mi][ni][1]));  // row = mb+mi*16+lane/4
            m1 = fmaxf(m1, fmaxf(acc[mi][ni][2], acc[mi][ni][3]));  // row + 8
        }
        m0 = fmaxf(m0, __shfl_xor_sync(0xffffffffu, m0, 1));
        m0 = fmaxf(m0, __shfl_xor_sync(0xffffffffu, m0, 2));
        m1 = fmaxf(m1, __shfl_xor_sync(0xffffffffu, m1, 1));
        m1 = fmaxf(m1, __shfl_xor_sync(0xffffffffu, m1, 2));
        if ((lane & 3) == 0) {
            int r = mb + mi * 16 + (lane >> 2);
            atomicMax(&smax[r], fkey(m0));
            atomicMax(&smax[r + 8], fkey(m1));
        }
    }
    __syncthreads();
    if (tid < BM) atomicMax(&g_rowmax[tileM * BM + tid], smax[tid]);
}

// ---------------- final: loss = mean(1 - rowmax) ----------------
__global__ void final_reduce_kernel(float* __restrict__ out) {
    __shared__ float red[256];
    int tid = threadIdx.x;
    float s = 0.f;
    for (int i = tid; i < N_DIM; i += 256) {
        unsigned int key = g_rowmax[i];
        float f = (key & 0x80000000u) ? __uint_as_float(key & 0x7FFFFFFFu)
                                      : __uint_as_float(~key);
        s += 1.0f - f;
    }
    red[tid] = s;
    __syncthreads();
    for (int off = 128; off > 0; off >>= 1) {
        if (tid < off) red[tid] += red[tid + off];
        __syncthreads();
    }
    if (tid == 0) out[0] = red[0] / (float)N_DIM;
}

// ---------------- launch ----------------
extern "C" void kernel_launch(void* const* d_in, const int* in_sizes, int n_in,
                              void* d_out, int out_size) {
    const float* F_r = (const float*)d_in[0];
    const float* F_s = (const float*)d_in[1];

    cudaFuncSetAttribute(nnfm_gemm_hmma, cudaFuncAttributeMaxDynamicSharedMemorySize, SMEM_TOTAL);

    init_rowmax_kernel<<<N_DIM / 256, 256>>>();
    colnorm_kernel<<<N_DIM / 64, 256>>>(F_r, 0);
    colnorm_kernel<<<N_DIM / 64, 256>>>(F_s, 1);

    dim3 tb(32, 8);
    dim3 tg(N_DIM / 32, C_DIM / 32);
    transpose_scale_kernel<<<tg, tb>>>(F_r, 0);
    transpose_scale_kernel<<<tg, tb>>>(F_s, 1);

    dim3 gg(N_DIM / BN, N_DIM / BM);   // 64 x 128
    nnfm_gemm_hmma<<<gg, 256, SMEM_TOTAL>>>();

    final_reduce_kernel<<<1, 256>>>((float*)d_out);
}